// round 6
// baseline (speedup 1.0000x reference)
#include <cuda_runtime.h>
#include <cuda_fp16.h>
#include <math.h>

#define Bb 16
#define Ss 512
#define Tt 512
#define Dd 512
#define Rr 8
#define NEG_BIG (-1e10f)
#define LOG2E 1.4426950408889634f

typedef unsigned long long u64;

// scratch (device globals; no allocation allowed)
__device__ float g_wn[Rr * Dd];            // normalized w (published by k_dots block 0)
__device__ float g_src_wt[Bb * Rr * Ss];   // [b,r,s]
__device__ float g_tar_wt[Bb * Rr * Tt];   // [b,r,t]

__device__ __forceinline__ float ex2(float x) {
    float y;
    asm("ex2.approx.f32 %0, %1;" : "=f"(y) : "f"(x));
    return y;
}
__device__ __forceinline__ u64 pk(float lo, float hi) {
    u64 d; asm("mov.b64 %0, {%1, %2};" : "=l"(d) : "f"(lo), "f"(hi)); return d;
}
__device__ __forceinline__ void upk(u64 p, float& lo, float& hi) {
    asm("mov.b64 {%0, %1}, %2;" : "=f"(lo), "=f"(hi) : "l"(p));
}
__device__ __forceinline__ u64 ffma2(u64 a, u64 b, u64 c) {
    u64 d; asm("fma.rn.f32x2 %0, %1, %2, %3;" : "=l"(d) : "l"(a), "l"(b), "l"(c)); return d;
}
__device__ __forceinline__ u64 fadd2(u64 a, u64 b) {
    u64 d; asm("add.rn.f32x2 %0, %1, %2;" : "=l"(d) : "l"(a), "l"(b)); return d;
}

// ---------------------------------------------------------------------------
// Kernel 1: normalize w in smem, then dot each embedding row with all 8 wn rows.
// 256 threads (8 warps), 4 rows/warp, double-buffered x loads, packed f32x2
// FMAs, butterfly reduction landing acc-index == lane (1 store per lane).
// ---------------------------------------------------------------------------
__global__ __launch_bounds__(256) void k_dots(const float* __restrict__ src,
                                              const float* __restrict__ tar,
                                              const float* __restrict__ w) {
    __shared__ float4 wn_s[Rr * Dd / 4];  // 16 KB
    __shared__ float  sc_s[Rr];
    int tid  = threadIdx.x;
    int warp = tid >> 5;
    int lane = tid & 31;

#pragma unroll
    for (int i = 0; i < 4; i++)
        wn_s[tid + 256 * i] = ((const float4*)w)[tid + 256 * i];
    __syncthreads();

    if (warp < Rr) {
        float ss = 0.f;
#pragma unroll
        for (int k = 0; k < 4; k++) {
            float4 x = wn_s[warp * 128 + lane + 32 * k];
            ss += x.x * x.x + x.y * x.y + x.z * x.z + x.w * x.w;
        }
#pragma unroll
        for (int off = 16; off; off >>= 1)
            ss += __shfl_xor_sync(0xffffffffu, ss, off);
        if (lane == 0) sc_s[warp] = 1.0f / fmaxf(sqrtf(ss), 1e-12f);
    }
    __syncthreads();

#pragma unroll
    for (int i = 0; i < 4; i++) {
        int idx = tid + 256 * i;
        float s = sc_s[idx >> 7];
        float4 v = wn_s[idx];
        v.x *= s; v.y *= s; v.z *= s; v.w *= s;
        wn_s[idx] = v;
    }
    __syncthreads();

    if (blockIdx.x == 0) {
#pragma unroll
        for (int i = 0; i < 4; i++)
            ((float4*)g_wn)[tid + 256 * i] = wn_s[tid + 256 * i];
    }

    int base = blockIdx.x * 32 + warp * 4;
    bool is_src = base < Bb * Ss;            // blocks never straddle (8192 % 32 == 0)
    const float* eb = is_src ? src : tar;
    int lbase = is_src ? base : base - Bb * Ss;

    u64 acc2[4][Rr];
#pragma unroll
    for (int rr = 0; rr < 4; rr++)
#pragma unroll
        for (int r = 0; r < Rr; r++) acc2[rr][r] = 0ull;

    float4 xa[4], xb[4];
#pragma unroll
    for (int rr = 0; rr < 4; rr++)
        xa[rr] = ((const float4*)(eb + (size_t)(lbase + rr) * Dd))[lane];

#pragma unroll
    for (int k = 0; k < 4; k++) {
        if (k < 3) {
#pragma unroll
            for (int rr = 0; rr < 4; rr++)
                xb[rr] = ((const float4*)(eb + (size_t)(lbase + rr) * Dd))[lane + 32 * (k + 1)];
        }
        u64 xp01[4], xp23[4];
#pragma unroll
        for (int rr = 0; rr < 4; rr++) {
            xp01[rr] = pk(xa[rr].x, xa[rr].y);
            xp23[rr] = pk(xa[rr].z, xa[rr].w);
        }
#pragma unroll
        for (int r = 0; r < Rr; r++) {
            float4 wv = wn_s[r * 128 + lane + 32 * k];
            u64 w01 = pk(wv.x, wv.y);
            u64 w23 = pk(wv.z, wv.w);
#pragma unroll
            for (int rr = 0; rr < 4; rr++) {
                acc2[rr][r] = ffma2(xp01[rr], w01, acc2[rr][r]);
                acc2[rr][r] = ffma2(xp23[rr], w23, acc2[rr][r]);
            }
        }
#pragma unroll
        for (int rr = 0; rr < 4; rr++) xa[rr] = xb[rr];
    }

    // fold even/odd, butterfly so final value for acc-index L lands at lane L
    float t[32];
#pragma unroll
    for (int rr = 0; rr < 4; rr++)
#pragma unroll
        for (int r = 0; r < Rr; r++) {
            float lo, hi;
            upk(acc2[rr][r], lo, hi);
            t[rr * 8 + r] = lo + hi;
        }

#pragma unroll
    for (int st = 0; st < 5; st++) {
        int off = 1 << st;
        int sel = lane & off;
#pragma unroll
        for (int j = 0; j < (16 >> st); j++) {
            float give = sel ? t[2 * j]     : t[2 * j + 1];
            float keep = sel ? t[2 * j + 1] : t[2 * j];
            float recv = __shfl_xor_sync(0xffffffffu, give, off);
            t[j] = keep + recv;
        }
    }

    {
        int rr = lane >> 3, r = lane & 7;
        int gid = lbase + rr;
        int bb = gid >> 9, s = gid & 511;
        float* gw = is_src ? g_src_wt : g_tar_wt;
        gw[((size_t)bb * Rr + r) * Ss + s] = t[0];
    }
}

// ---------------------------------------------------------------------------
// Kernel 2 (fused attention + output): grid = B*(S/16) = 512 blocks, 512 thr.
// quarter q = tid>>7 (t-range), r = (tid>>4)&7, j = tid&15.
// Fast path: analytic max (a*vmax / a*vmin, exact: scalar fp multiply is
// monotone), pure-f32 ex2 (XU pipe minimal: 1 op/elt), packed f32x2 FMAs,
// split accumulators. Slow path: general two-pass fp32 (block-uniform).
// Phase B: out tile [16 s][512 d] = c · wn with wn in registers.
// ---------------------------------------------------------------------------
__global__ __launch_bounds__(512) void k_attn_out(const float* __restrict__ src_mask,
                                                  const float* __restrict__ tar_mask,
                                                  float* __restrict__ out) {
    __shared__ float v_s[Rr * Tt];    // 16 KB
    __shared__ float tm_s[Tt];
    __shared__ float a_s[Rr * 16];
    __shared__ float sm_s[16];
    __shared__ float ps[512], pa[512], pm[512];
    __shared__ float c_s[16 * Rr];
    __shared__ float red_max[Rr], red_min[Rr];
    __shared__ int   s_tmok, s_smok;

    int b   = blockIdx.x >> 5;
    int s0  = (blockIdx.x & 31) * 16;
    int tid = threadIdx.x;
    int warp = tid >> 5, lane = tid & 31;
    int q    = tid >> 7;          // t quarter
    int r    = (tid >> 4) & 7;
    int j    = tid & 15;

    const float4* vsrc = (const float4*)(g_tar_wt + (size_t)b * Rr * Tt);
    ((float4*)v_s)[tid]       = vsrc[tid];
    ((float4*)v_s)[tid + 512] = vsrc[tid + 512];
    if (tid < 128) ((float4*)tm_s)[tid] = ((const float4*)(tar_mask + (size_t)b * Tt))[tid];
    if (tid < 128) a_s[tid] = g_src_wt[((size_t)b * Rr + (tid >> 4)) * Ss + s0 + (tid & 15)];
    if (tid < 16)  sm_s[tid] = src_mask[(size_t)b * Ss + s0 + tid];
    __syncthreads();

    if (warp < Rr) {
        float cmax = -3.4e38f, cmin = 3.4e38f;
#pragma unroll
        for (int k = 0; k < 16; k++) {
            float v = v_s[warp * 512 + lane + 32 * k];
            cmax = fmaxf(cmax, v);
            cmin = fminf(cmin, v);
        }
#pragma unroll
        for (int off = 16; off; off >>= 1) {
            cmax = fmaxf(cmax, __shfl_xor_sync(0xffffffffu, cmax, off));
            cmin = fminf(cmin, __shfl_xor_sync(0xffffffffu, cmin, off));
        }
        if (lane == 0) { red_max[warp] = cmax; red_min[warp] = cmin; }
    } else if (warp == 8) {
        int one = 1;
#pragma unroll
        for (int k = 0; k < 16; k++)
            one &= (tm_s[lane + 32 * k] == 1.0f);
        one = (__ballot_sync(0xffffffffu, one) == 0xffffffffu);
        if (lane == 0) s_tmok = one;
    } else if (warp == 9) {
        int one = (lane < 16) ? (sm_s[lane] == 1.0f) : 1;
        one = (__ballot_sync(0xffffffffu, one) == 0xffffffffu);
        if (lane == 0) s_smok = one;
    }
    __syncthreads();

    float a  = a_s[tid & 127];
    const float4* vv = (const float4*)(v_s + r * Tt) + q * 32;   // 128 t per quarter
    const float4* tt = (const float4*)tm_s + q * 32;

    if (s_tmok && s_smok) {
        float m   = (a >= 0.f) ? a * red_max[r] : a * red_min[r];
        float a2  = a * LOG2E;
        float nm2 = -m * LOG2E;
        u64 a2p  = pk(a2, a2);
        u64 nm2p = pk(nm2, nm2);
        u64 sum2a = 0ull, sum2b = 0ull, acc2a = 0ull, acc2b = 0ull;
#pragma unroll 8
        for (int t4 = 0; t4 < 32; t4++) {
            float4 v = vv[t4];
            u64 v01 = pk(v.x, v.y);
            u64 v23 = pk(v.z, v.w);
            float x0, x1, x2, x3;
            upk(ffma2(a2p, v01, nm2p), x0, x1);
            upk(ffma2(a2p, v23, nm2p), x2, x3);
            float e0 = ex2(x0);
            float e1 = ex2(x1);
            float e2 = ex2(x2);
            float e3 = ex2(x3);
            u64 e01 = pk(e0, e1);
            u64 e23 = pk(e2, e3);
            sum2a = fadd2(sum2a, e01);
            sum2b = fadd2(sum2b, e23);
            acc2a = ffma2(e01, v01, acc2a);
            acc2b = ffma2(e23, v23, acc2b);
        }
        float sl, sh, al, ah, bl, bh;
        upk(fadd2(sum2a, sum2b), sl, sh);
        upk(acc2a, al, ah);
        upk(acc2b, bl, bh);
        ps[tid] = sl + sh;
        pa[tid] = (al + ah) + (bl + bh);
        __syncthreads();
    } else {
        float sm = sm_s[j];
        float sum = 0.f, acc = 0.f;
        float m = -3.4e38f;
#pragma unroll 8
        for (int t4 = 0; t4 < 32; t4++) {
            float4 v = vv[t4], tm = tt[t4];
            float x0 = fmaf(a, v.x, fmaf(sm * tm.x, 1e10f, NEG_BIG));
            float x1 = fmaf(a, v.y, fmaf(sm * tm.y, 1e10f, NEG_BIG));
            float x2 = fmaf(a, v.z, fmaf(sm * tm.z, 1e10f, NEG_BIG));
            float x3 = fmaf(a, v.w, fmaf(sm * tm.w, 1e10f, NEG_BIG));
            m = fmaxf(m, fmaxf(fmaxf(x0, x1), fmaxf(x2, x3)));
        }
        pm[tid] = m;
        __syncthreads();
        {
            int rj = tid & 127;
            m = fmaxf(fmaxf(pm[rj], pm[rj + 128]), fmaxf(pm[rj + 256], pm[rj + 384]));
        }
#pragma unroll 8
        for (int t4 = 0; t4 < 32; t4++) {
            float4 v = vv[t4], tm = tt[t4];
            float x0 = fmaf(a, v.x, fmaf(sm * tm.x, 1e10f, NEG_BIG));
            float x1 = fmaf(a, v.y, fmaf(sm * tm.y, 1e10f, NEG_BIG));
            float x2 = fmaf(a, v.z, fmaf(sm * tm.z, 1e10f, NEG_BIG));
            float x3 = fmaf(a, v.w, fmaf(sm * tm.w, 1e10f, NEG_BIG));
            float e0 = ex2((x0 - m) * LOG2E);
            float e1 = ex2((x1 - m) * LOG2E);
            float e2 = ex2((x2 - m) * LOG2E);
            float e3 = ex2((x3 - m) * LOG2E);
            sum += e0 + e1 + e2 + e3;
            acc = fmaf(e0, v.x, acc);
            acc = fmaf(e1, v.y, acc);
            acc = fmaf(e2, v.z, acc);
            acc = fmaf(e3, v.w, acc);
        }
        ps[tid] = sum; pa[tid] = acc;
        __syncthreads();
    }

    if (tid < 128) {
        float S = (ps[tid] + ps[tid + 128]) + (ps[tid + 256] + ps[tid + 384]);
        float A = (pa[tid] + pa[tid + 128]) + (pa[tid + 256] + pa[tid + 384]);
        c_s[(tid & 15) * Rr + (tid >> 4)] = A / S;
    }
    __syncthreads();

    // Phase B: out tile [16 s][512 d] = c · wn
    {
        int d4 = tid & 127;
        int jg = tid >> 7;
        float4 wv[Rr];
#pragma unroll
        for (int rr = 0; rr < Rr; rr++) wv[rr] = ((const float4*)g_wn)[rr * 128 + d4];

        float4* out4 = (float4*)out;
#pragma unroll
        for (int k = 0; k < 4; k++) {
            int jj = jg + 4 * k;
            float4 o = make_float4(0.f, 0.f, 0.f, 0.f);
#pragma unroll
            for (int rr = 0; rr < Rr; rr++) {
                float c = c_s[jj * Rr + rr];
                o.x = fmaf(c, wv[rr].x, o.x);
                o.y = fmaf(c, wv[rr].y, o.y);
                o.z = fmaf(c, wv[rr].z, o.z);
                o.w = fmaf(c, wv[rr].w, o.w);
            }
            out4[((size_t)b * Ss + s0 + jj) * (Dd / 4) + d4] = o;
        }
    }
}

// ---------------------------------------------------------------------------
extern "C" void kernel_launch(void* const* d_in, const int* in_sizes, int n_in,
                              void* d_out, int out_size) {
    const float* src_emb  = (const float*)d_in[0];
    const float* tar_emb  = (const float*)d_in[1];
    const float* src_mask = (const float*)d_in[2];
    const float* tar_mask = (const float*)d_in[3];
    const float* w        = (const float*)d_in[4];
    float* out            = (float*)d_out;

    k_dots<<<(Bb * Ss + Bb * Tt) / 32, 256>>>(src_emb, tar_emb, w);
    k_attn_out<<<Bb * (Ss / 16), 512>>>(src_mask, tar_mask, out);
}

// round 7
// speedup vs baseline: 1.0106x; 1.0106x over previous
#include <cuda_runtime.h>
#include <cuda_fp16.h>
#include <math.h>

#define Bb 16
#define Ss 512
#define Tt 512
#define Dd 512
#define Rr 8
#define NEG_BIG (-1e10f)
#define LOG2E 1.4426950408889634f

typedef unsigned long long u64;

// scratch (device globals; no allocation allowed)
__device__ float g_wn[Rr * Dd];            // normalized w (published by k_dots block 0)
__device__ float g_src_wt[Bb * Rr * Ss];   // [b,r,s]
__device__ float g_tar_wt[Bb * Rr * Tt];   // [b,r,t]

__device__ __forceinline__ float ex2(float x) {
    float y;
    asm("ex2.approx.f32 %0, %1;" : "=f"(y) : "f"(x));
    return y;
}
__device__ __forceinline__ u64 pk(float lo, float hi) {
    u64 d; asm("mov.b64 %0, {%1, %2};" : "=l"(d) : "f"(lo), "f"(hi)); return d;
}
__device__ __forceinline__ void upk(u64 p, float& lo, float& hi) {
    asm("mov.b64 {%0, %1}, %2;" : "=f"(lo), "=f"(hi) : "l"(p));
}
__device__ __forceinline__ u64 ffma2(u64 a, u64 b, u64 c) {
    u64 d; asm("fma.rn.f32x2 %0, %1, %2, %3;" : "=l"(d) : "l"(a), "l"(b), "l"(c)); return d;
}
__device__ __forceinline__ u64 fadd2(u64 a, u64 b) {
    u64 d; asm("add.rn.f32x2 %0, %1, %2;" : "=l"(d) : "l"(a), "l"(b)); return d;
}
__device__ __forceinline__ unsigned ex2h2(unsigned x) {
    unsigned y; asm("ex2.approx.f16x2 %0, %1;" : "=r"(y) : "r"(x)); return y;
}

// ---------------------------------------------------------------------------
// Kernel 1: normalize w in smem, then dot each embedding row with all 8 wn rows.
// 256 threads (8 warps), 2 rows/warp => acc fits in 32 regs => high occupancy
// (the old 4-rows/warp variant needed 64 accumulator regs and capped at ~2
// blocks/SM, exposing L2 latency). 1024 blocks x 16 rows = 16384 rows.
// ---------------------------------------------------------------------------
__global__ __launch_bounds__(256, 3) void k_dots(const float* __restrict__ src,
                                                 const float* __restrict__ tar,
                                                 const float* __restrict__ w) {
    __shared__ float4 wn_s[Rr * Dd / 4];  // 16 KB
    __shared__ float  sc_s[Rr];
    int tid  = threadIdx.x;
    int warp = tid >> 5;
    int lane = tid & 31;

#pragma unroll
    for (int i = 0; i < 4; i++)
        wn_s[tid + 256 * i] = ((const float4*)w)[tid + 256 * i];
    __syncthreads();

    if (warp < Rr) {
        float ss = 0.f;
#pragma unroll
        for (int k = 0; k < 4; k++) {
            float4 x = wn_s[warp * 128 + lane + 32 * k];
            ss += x.x * x.x + x.y * x.y + x.z * x.z + x.w * x.w;
        }
#pragma unroll
        for (int off = 16; off; off >>= 1)
            ss += __shfl_xor_sync(0xffffffffu, ss, off);
        if (lane == 0) sc_s[warp] = 1.0f / fmaxf(sqrtf(ss), 1e-12f);
    }
    __syncthreads();

#pragma unroll
    for (int i = 0; i < 4; i++) {
        int idx = tid + 256 * i;
        float s = sc_s[idx >> 7];
        float4 v = wn_s[idx];
        v.x *= s; v.y *= s; v.z *= s; v.w *= s;
        wn_s[idx] = v;
    }
    __syncthreads();

    if (blockIdx.x == 0) {
#pragma unroll
        for (int i = 0; i < 4; i++)
            ((float4*)g_wn)[tid + 256 * i] = wn_s[tid + 256 * i];
    }

    int base = blockIdx.x * 16 + warp * 2;
    bool is_src = base < Bb * Ss;            // blocks never straddle (8192 % 16 == 0)
    const float* eb = is_src ? src : tar;
    int lbase = is_src ? base : base - Bb * Ss;

    u64 acc2[2][Rr];
#pragma unroll
    for (int rr = 0; rr < 2; rr++)
#pragma unroll
        for (int r = 0; r < Rr; r++) acc2[rr][r] = 0ull;

#pragma unroll
    for (int k = 0; k < 4; k++) {
        u64 xp01[2], xp23[2];
#pragma unroll
        for (int rr = 0; rr < 2; rr++) {
            float4 x = ((const float4*)(eb + (size_t)(lbase + rr) * Dd))[lane + 32 * k];
            xp01[rr] = pk(x.x, x.y);
            xp23[rr] = pk(x.z, x.w);
        }
#pragma unroll
        for (int r = 0; r < Rr; r++) {
            float4 wv = wn_s[r * 128 + lane + 32 * k];
            u64 w01 = pk(wv.x, wv.y);
            u64 w23 = pk(wv.z, wv.w);
#pragma unroll
            for (int rr = 0; rr < 2; rr++) {
                acc2[rr][r] = ffma2(xp01[rr], w01, acc2[rr][r]);
                acc2[rr][r] = ffma2(xp23[rr], w23, acc2[rr][r]);
            }
        }
    }

    // fold even/odd, padded butterfly so acc-index L lands at lane L (L<16)
    float t[32];
#pragma unroll
    for (int rr = 0; rr < 2; rr++)
#pragma unroll
        for (int r = 0; r < Rr; r++) {
            float lo, hi;
            upk(acc2[rr][r], lo, hi);
            t[rr * 8 + r] = lo + hi;
        }
#pragma unroll
    for (int i = 16; i < 32; i++) t[i] = 0.f;

#pragma unroll
    for (int st = 0; st < 5; st++) {
        int off = 1 << st;
        int sel = lane & off;
#pragma unroll
        for (int j = 0; j < (16 >> st); j++) {
            float give = sel ? t[2 * j]     : t[2 * j + 1];
            float keep = sel ? t[2 * j + 1] : t[2 * j];
            float recv = __shfl_xor_sync(0xffffffffu, give, off);
            t[j] = keep + recv;
        }
    }

    if (lane < 16) {
        int rr = lane >> 3, r = lane & 7;
        int gid = lbase + rr;
        int bb = gid >> 9, s = gid & 511;
        float* gw = is_src ? g_src_wt : g_tar_wt;
        gw[((size_t)bb * Rr + r) * Ss + s] = t[0];
    }
}

// ---------------------------------------------------------------------------
// Kernel 2 (fused attention + output): grid = B*(S/32) = 256 blocks, 512 thr.
// half = tid>>8, r = (tid>>5)&7, j = tid&31. Fast path: analytic max +
// f16x2 exp (2 exps / MUFU op) with packed-f32x2 score & accumulation.
// Slow path: general two-pass fp32 (block-uniform branch).
// Phase B: out tile [32 s][512 d] = c · wn with wn in registers.
// ---------------------------------------------------------------------------
__global__ __launch_bounds__(512) void k_attn_out(const float* __restrict__ src_mask,
                                                  const float* __restrict__ tar_mask,
                                                  float* __restrict__ out) {
    __shared__ float v_s[Rr * Tt];    // 16 KB
    __shared__ float tm_s[Tt];
    __shared__ float a_s[Rr * 32];
    __shared__ float sm_s[32];
    __shared__ float ps[512], pa[512], pm[512];
    __shared__ float c_s[32 * Rr];
    __shared__ float red_max[Rr], red_min[Rr];
    __shared__ int   s_tmok, s_smok;

    int b   = blockIdx.x >> 4;
    int s0  = (blockIdx.x & 15) * 32;
    int tid = threadIdx.x;
    int warp = tid >> 5, lane = tid & 31;
    int half = tid >> 8;
    int r    = (tid >> 5) & 7;
    int j    = tid & 31;

    const float4* vsrc = (const float4*)(g_tar_wt + (size_t)b * Rr * Tt);
    ((float4*)v_s)[tid]       = vsrc[tid];
    ((float4*)v_s)[tid + 512] = vsrc[tid + 512];
    if (tid < 128) ((float4*)tm_s)[tid] = ((const float4*)(tar_mask + (size_t)b * Tt))[tid];
    if (tid < 256) a_s[tid] = g_src_wt[((size_t)b * Rr + (tid >> 5)) * Ss + s0 + (tid & 31)];
    if (tid < 32)  sm_s[tid] = src_mask[(size_t)b * Ss + s0 + tid];
    __syncthreads();

    if (warp < Rr) {
        float cmax = -3.4e38f, cmin = 3.4e38f;
#pragma unroll
        for (int k = 0; k < 16; k++) {
            float v = v_s[warp * 512 + lane + 32 * k];
            cmax = fmaxf(cmax, v);
            cmin = fminf(cmin, v);
        }
#pragma unroll
        for (int off = 16; off; off >>= 1) {
            cmax = fmaxf(cmax, __shfl_xor_sync(0xffffffffu, cmax, off));
            cmin = fminf(cmin, __shfl_xor_sync(0xffffffffu, cmin, off));
        }
        if (lane == 0) { red_max[warp] = cmax; red_min[warp] = cmin; }
    } else if (warp == 8) {
        int one = 1;
#pragma unroll
        for (int k = 0; k < 16; k++)
            one &= (tm_s[lane + 32 * k] == 1.0f);
        one = (__ballot_sync(0xffffffffu, one) == 0xffffffffu);
        if (lane == 0) s_tmok = one;
    } else if (warp == 9) {
        int one = (sm_s[lane] == 1.0f);
        one = (__ballot_sync(0xffffffffu, one) == 0xffffffffu);
        if (lane == 0) s_smok = one;
    }
    __syncthreads();

    float a  = a_s[tid & 255];
    const float4* vv = (const float4*)(v_s + r * Tt) + half * 64;
    const float4* tt = (const float4*)tm_s + half * 64;

    if (s_tmok && s_smok) {
        float m   = (a >= 0.f) ? a * red_max[r] : a * red_min[r];
        float a2  = a * LOG2E;
        float nm2 = -m * LOG2E;
        u64 a2p  = pk(a2, a2);
        u64 nm2p = pk(nm2, nm2);
        u64 sum2a = 0ull, sum2b = 0ull, acc2a = 0ull, acc2b = 0ull;
#pragma unroll 4
        for (int t4 = 0; t4 < 64; t4++) {
            float4 v = vv[t4];
            u64 v01 = pk(v.x, v.y);
            u64 v23 = pk(v.z, v.w);
            u64 x01 = ffma2(a2p, v01, nm2p);
            u64 x23 = ffma2(a2p, v23, nm2p);
            float x0, x1, x2, x3;
            upk(x01, x0, x1);
            upk(x23, x2, x3);
            __half2 h01 = __floats2half2_rn(x0, x1);
            __half2 h23 = __floats2half2_rn(x2, x3);
            unsigned u01 = ex2h2(*reinterpret_cast<unsigned*>(&h01));
            unsigned u23 = ex2h2(*reinterpret_cast<unsigned*>(&h23));
            float2 e01 = __half22float2(*reinterpret_cast<__half2*>(&u01));
            float2 e23 = __half22float2(*reinterpret_cast<__half2*>(&u23));
            u64 e01p = pk(e01.x, e01.y);
            u64 e23p = pk(e23.x, e23.y);
            sum2a = fadd2(sum2a, e01p);
            sum2b = fadd2(sum2b, e23p);
            acc2a = ffma2(e01p, v01, acc2a);
            acc2b = ffma2(e23p, v23, acc2b);
        }
        float sl, sh, al, ah, bl, bh;
        upk(fadd2(sum2a, sum2b), sl, sh);
        upk(acc2a, al, ah);
        upk(acc2b, bl, bh);
        ps[tid] = sl + sh;
        pa[tid] = (al + ah) + (bl + bh);
        __syncthreads();
    } else {
        float sm = sm_s[j];
        float sum = 0.f, acc = 0.f;
        float m = -3.4e38f;
#pragma unroll 4
        for (int t4 = 0; t4 < 64; t4++) {
            float4 v = vv[t4], tm = tt[t4];
            float x0 = fmaf(a, v.x, fmaf(sm * tm.x, 1e10f, NEG_BIG));
            float x1 = fmaf(a, v.y, fmaf(sm * tm.y, 1e10f, NEG_BIG));
            float x2 = fmaf(a, v.z, fmaf(sm * tm.z, 1e10f, NEG_BIG));
            float x3 = fmaf(a, v.w, fmaf(sm * tm.w, 1e10f, NEG_BIG));
            m = fmaxf(m, fmaxf(fmaxf(x0, x1), fmaxf(x2, x3)));
        }
        pm[tid] = m;
        __syncthreads();
        m = fmaxf(pm[tid], pm[tid ^ 256]);
#pragma unroll 4
        for (int t4 = 0; t4 < 64; t4++) {
            float4 v = vv[t4], tm = tt[t4];
            float x0 = fmaf(a, v.x, fmaf(sm * tm.x, 1e10f, NEG_BIG));
            float x1 = fmaf(a, v.y, fmaf(sm * tm.y, 1e10f, NEG_BIG));
            float x2 = fmaf(a, v.z, fmaf(sm * tm.z, 1e10f, NEG_BIG));
            float x3 = fmaf(a, v.w, fmaf(sm * tm.w, 1e10f, NEG_BIG));
            float e0 = ex2((x0 - m) * LOG2E);
            float e1 = ex2((x1 - m) * LOG2E);
            float e2 = ex2((x2 - m) * LOG2E);
            float e3 = ex2((x3 - m) * LOG2E);
            sum += e0 + e1 + e2 + e3;
            acc = fmaf(e0, v.x, acc);
            acc = fmaf(e1, v.y, acc);
            acc = fmaf(e2, v.z, acc);
            acc = fmaf(e3, v.w, acc);
        }
        ps[tid] = sum; pa[tid] = acc;
        __syncthreads();
    }

    if (tid < 256) {
        float S = ps[tid] + ps[tid + 256];
        float A = pa[tid] + pa[tid + 256];
        c_s[(tid & 31) * Rr + (tid >> 5)] = A / S;
    }
    __syncthreads();

    // Phase B: out tile [32 s][512 d] = c · wn
    {
        int d4 = tid & 127;
        int jg = tid >> 7;
        float4 wv[Rr];
#pragma unroll
        for (int rr = 0; rr < Rr; rr++) wv[rr] = ((const float4*)g_wn)[rr * 128 + d4];

        float4* out4 = (float4*)out;
#pragma unroll
        for (int k = 0; k < 8; k++) {
            int jj = jg + 4 * k;
            float4 o = make_float4(0.f, 0.f, 0.f, 0.f);
#pragma unroll
            for (int rr = 0; rr < Rr; rr++) {
                float c = c_s[jj * Rr + rr];
                o.x = fmaf(c, wv[rr].x, o.x);
                o.y = fmaf(c, wv[rr].y, o.y);
                o.z = fmaf(c, wv[rr].z, o.z);
                o.w = fmaf(c, wv[rr].w, o.w);
            }
            out4[((size_t)b * Ss + s0 + jj) * (Dd / 4) + d4] = o;
        }
    }
}

// ---------------------------------------------------------------------------
extern "C" void kernel_launch(void* const* d_in, const int* in_sizes, int n_in,
                              void* d_out, int out_size) {
    const float* src_emb  = (const float*)d_in[0];
    const float* tar_emb  = (const float*)d_in[1];
    const float* src_mask = (const float*)d_in[2];
    const float* tar_mask = (const float*)d_in[3];
    const float* w        = (const float*)d_in[4];
    float* out            = (float*)d_out;

    k_dots<<<(Bb * Ss + Bb * Tt) / 16, 256>>>(src_emb, tar_emb, w);
    k_attn_out<<<Bb * (Ss / 32), 512>>>(src_mask, tar_mask, out);
}

// round 8
// speedup vs baseline: 1.1310x; 1.1190x over previous
#include <cuda_runtime.h>
#include <cuda_fp16.h>
#include <math.h>

#define Bb 16
#define Ss 512
#define Tt 512
#define Dd 512
#define Rr 8
#define NEG_BIG (-1e10f)
#define LOG2E 1.4426950408889634f

typedef unsigned long long u64;

// scratch (device globals; no allocation allowed)
__device__ float g_wn[Rr * Dd];            // normalized w (published by k_dots block 0)
__device__ float g_src_wt[Bb * Rr * Ss];   // [b,r,s]
__device__ float g_tar_wt[Bb * Rr * Tt];   // [b,r,t]

__device__ __forceinline__ float ex2(float x) {
    float y;
    asm("ex2.approx.f32 %0, %1;" : "=f"(y) : "f"(x));
    return y;
}
__device__ __forceinline__ u64 pk(float lo, float hi) {
    u64 d; asm("mov.b64 %0, {%1, %2};" : "=l"(d) : "f"(lo), "f"(hi)); return d;
}
__device__ __forceinline__ void upk(u64 p, float& lo, float& hi) {
    asm("mov.b64 {%0, %1}, %2;" : "=f"(lo), "=f"(hi) : "l"(p));
}
__device__ __forceinline__ u64 ffma2(u64 a, u64 b, u64 c) {
    u64 d; asm("fma.rn.f32x2 %0, %1, %2, %3;" : "=l"(d) : "l"(a), "l"(b), "l"(c)); return d;
}
__device__ __forceinline__ u64 fadd2(u64 a, u64 b) {
    u64 d; asm("add.rn.f32x2 %0, %1, %2;" : "=l"(d) : "l"(a), "l"(b)); return d;
}
__device__ __forceinline__ unsigned ex2h2(unsigned x) {
    unsigned y; asm("ex2.approx.f16x2 %0, %1;" : "=r"(y) : "r"(x)); return y;
}

// ---------------------------------------------------------------------------
// Kernel 1: normalize w in smem, then dot each embedding row with all 8 wn rows.
// 256 threads (8 warps), 4 rows/warp (w-LDS reuse 4), x loaded inside the
// k-loop (register-lean: no double-buffer, no spills), packed f32x2 FMAs.
// __launch_bounds__(256,2): 128-reg cap, 2 blocks/SM. 512 blocks x 32 rows.
// ---------------------------------------------------------------------------
__global__ __launch_bounds__(256, 2) void k_dots(const float* __restrict__ src,
                                                 const float* __restrict__ tar,
                                                 const float* __restrict__ w) {
    __shared__ float4 wn_s[Rr * Dd / 4];  // 16 KB
    __shared__ float  sc_s[Rr];
    int tid  = threadIdx.x;
    int warp = tid >> 5;
    int lane = tid & 31;

#pragma unroll
    for (int i = 0; i < 4; i++)
        wn_s[tid + 256 * i] = ((const float4*)w)[tid + 256 * i];
    __syncthreads();

    if (warp < Rr) {
        float ss = 0.f;
#pragma unroll
        for (int k = 0; k < 4; k++) {
            float4 x = wn_s[warp * 128 + lane + 32 * k];
            ss += x.x * x.x + x.y * x.y + x.z * x.z + x.w * x.w;
        }
#pragma unroll
        for (int off = 16; off; off >>= 1)
            ss += __shfl_xor_sync(0xffffffffu, ss, off);
        if (lane == 0) sc_s[warp] = 1.0f / fmaxf(sqrtf(ss), 1e-12f);
    }
    __syncthreads();

#pragma unroll
    for (int i = 0; i < 4; i++) {
        int idx = tid + 256 * i;
        float s = sc_s[idx >> 7];
        float4 v = wn_s[idx];
        v.x *= s; v.y *= s; v.z *= s; v.w *= s;
        wn_s[idx] = v;
    }
    __syncthreads();

    if (blockIdx.x == 0) {
#pragma unroll
        for (int i = 0; i < 4; i++)
            ((float4*)g_wn)[tid + 256 * i] = wn_s[tid + 256 * i];
    }

    int base = blockIdx.x * 32 + warp * 4;
    bool is_src = base < Bb * Ss;            // blocks never straddle (8192 % 32 == 0)
    const float* eb = is_src ? src : tar;
    int lbase = is_src ? base : base - Bb * Ss;

    u64 acc2[4][Rr];
#pragma unroll
    for (int rr = 0; rr < 4; rr++)
#pragma unroll
        for (int r = 0; r < Rr; r++) acc2[rr][r] = 0ull;

#pragma unroll
    for (int k = 0; k < 4; k++) {
        u64 xp01[4], xp23[4];
#pragma unroll
        for (int rr = 0; rr < 4; rr++) {
            float4 x = ((const float4*)(eb + (size_t)(lbase + rr) * Dd))[lane + 32 * k];
            xp01[rr] = pk(x.x, x.y);
            xp23[rr] = pk(x.z, x.w);
        }
#pragma unroll
        for (int r = 0; r < Rr; r++) {
            float4 wv = wn_s[r * 128 + lane + 32 * k];
            u64 w01 = pk(wv.x, wv.y);
            u64 w23 = pk(wv.z, wv.w);
#pragma unroll
            for (int rr = 0; rr < 4; rr++) {
                acc2[rr][r] = ffma2(xp01[rr], w01, acc2[rr][r]);
                acc2[rr][r] = ffma2(xp23[rr], w23, acc2[rr][r]);
            }
        }
    }

    // fold even/odd, butterfly so final value for acc-index L lands at lane L
    float t[32];
#pragma unroll
    for (int rr = 0; rr < 4; rr++)
#pragma unroll
        for (int r = 0; r < Rr; r++) {
            float lo, hi;
            upk(acc2[rr][r], lo, hi);
            t[rr * 8 + r] = lo + hi;
        }

#pragma unroll
    for (int st = 0; st < 5; st++) {
        int off = 1 << st;
        int sel = lane & off;
#pragma unroll
        for (int j = 0; j < (16 >> st); j++) {
            float give = sel ? t[2 * j]     : t[2 * j + 1];
            float keep = sel ? t[2 * j + 1] : t[2 * j];
            float recv = __shfl_xor_sync(0xffffffffu, give, off);
            t[j] = keep + recv;
        }
    }

    {
        int rr = lane >> 3, r = lane & 7;
        int gid = lbase + rr;
        int bb = gid >> 9, s = gid & 511;
        float* gw = is_src ? g_src_wt : g_tar_wt;
        gw[((size_t)bb * Rr + r) * Ss + s] = t[0];
    }
}

// ---------------------------------------------------------------------------
// Kernel 2 (fused attention + output): grid = B*(S/32) = 256 blocks, 512 thr.
// half = tid>>8, r = (tid>>5)&7, j = tid&31. Fast path: analytic max +
// f16x2 exp (2 exps / MUFU op) with packed-f32x2 score & accumulation.
// Slow path: general two-pass fp32 (block-uniform branch).
// Phase B: out tile [32 s][512 d] = c · wn with wn in registers.
// ---------------------------------------------------------------------------
__global__ __launch_bounds__(512, 2) void k_attn_out(const float* __restrict__ src_mask,
                                                     const float* __restrict__ tar_mask,
                                                     float* __restrict__ out) {
    __shared__ float v_s[Rr * Tt];    // 16 KB
    __shared__ float tm_s[Tt];
    __shared__ float a_s[Rr * 32];
    __shared__ float sm_s[32];
    __shared__ float ps[512], pa[512], pm[512];
    __shared__ float c_s[32 * Rr];
    __shared__ float red_max[Rr], red_min[Rr];
    __shared__ int   s_tmok, s_smok;

    int b   = blockIdx.x >> 4;
    int s0  = (blockIdx.x & 15) * 32;
    int tid = threadIdx.x;
    int warp = tid >> 5, lane = tid & 31;
    int half = tid >> 8;
    int r    = (tid >> 5) & 7;
    int j    = tid & 31;

    const float4* vsrc = (const float4*)(g_tar_wt + (size_t)b * Rr * Tt);
    ((float4*)v_s)[tid]       = vsrc[tid];
    ((float4*)v_s)[tid + 512] = vsrc[tid + 512];
    if (tid < 128) ((float4*)tm_s)[tid] = ((const float4*)(tar_mask + (size_t)b * Tt))[tid];
    if (tid < 256) a_s[tid] = g_src_wt[((size_t)b * Rr + (tid >> 5)) * Ss + s0 + (tid & 31)];
    if (tid < 32)  sm_s[tid] = src_mask[(size_t)b * Ss + s0 + tid];
    __syncthreads();

    if (warp < Rr) {
        float cmax = -3.4e38f, cmin = 3.4e38f;
#pragma unroll
        for (int k = 0; k < 16; k++) {
            float v = v_s[warp * 512 + lane + 32 * k];
            cmax = fmaxf(cmax, v);
            cmin = fminf(cmin, v);
        }
#pragma unroll
        for (int off = 16; off; off >>= 1) {
            cmax = fmaxf(cmax, __shfl_xor_sync(0xffffffffu, cmax, off));
            cmin = fminf(cmin, __shfl_xor_sync(0xffffffffu, cmin, off));
        }
        if (lane == 0) { red_max[warp] = cmax; red_min[warp] = cmin; }
    } else if (warp == 8) {
        int one = 1;
#pragma unroll
        for (int k = 0; k < 16; k++)
            one &= (tm_s[lane + 32 * k] == 1.0f);
        one = (__ballot_sync(0xffffffffu, one) == 0xffffffffu);
        if (lane == 0) s_tmok = one;
    } else if (warp == 9) {
        int one = (sm_s[lane] == 1.0f);
        one = (__ballot_sync(0xffffffffu, one) == 0xffffffffu);
        if (lane == 0) s_smok = one;
    }
    __syncthreads();

    float a  = a_s[tid & 255];
    const float4* vv = (const float4*)(v_s + r * Tt) + half * 64;
    const float4* tt = (const float4*)tm_s + half * 64;

    if (s_tmok && s_smok) {
        float m   = (a >= 0.f) ? a * red_max[r] : a * red_min[r];
        float a2  = a * LOG2E;
        float nm2 = -m * LOG2E;
        u64 a2p  = pk(a2, a2);
        u64 nm2p = pk(nm2, nm2);
        u64 sum2a = 0ull, sum2b = 0ull, acc2a = 0ull, acc2b = 0ull;
#pragma unroll 4
        for (int t4 = 0; t4 < 64; t4++) {
            float4 v = vv[t4];
            u64 v01 = pk(v.x, v.y);
            u64 v23 = pk(v.z, v.w);
            u64 x01 = ffma2(a2p, v01, nm2p);
            u64 x23 = ffma2(a2p, v23, nm2p);
            float x0, x1, x2, x3;
            upk(x01, x0, x1);
            upk(x23, x2, x3);
            __half2 h01 = __floats2half2_rn(x0, x1);
            __half2 h23 = __floats2half2_rn(x2, x3);
            unsigned u01 = ex2h2(*reinterpret_cast<unsigned*>(&h01));
            unsigned u23 = ex2h2(*reinterpret_cast<unsigned*>(&h23));
            float2 e01 = __half22float2(*reinterpret_cast<__half2*>(&u01));
            float2 e23 = __half22float2(*reinterpret_cast<__half2*>(&u23));
            u64 e01p = pk(e01.x, e01.y);
            u64 e23p = pk(e23.x, e23.y);
            sum2a = fadd2(sum2a, e01p);
            sum2b = fadd2(sum2b, e23p);
            acc2a = ffma2(e01p, v01, acc2a);
            acc2b = ffma2(e23p, v23, acc2b);
        }
        float sl, sh, al, ah, bl, bh;
        upk(fadd2(sum2a, sum2b), sl, sh);
        upk(acc2a, al, ah);
        upk(acc2b, bl, bh);
        ps[tid] = sl + sh;
        pa[tid] = (al + ah) + (bl + bh);
        __syncthreads();
    } else {
        float sm = sm_s[j];
        float sum = 0.f, acc = 0.f;
        float m = -3.4e38f;
#pragma unroll 4
        for (int t4 = 0; t4 < 64; t4++) {
            float4 v = vv[t4], tm = tt[t4];
            float x0 = fmaf(a, v.x, fmaf(sm * tm.x, 1e10f, NEG_BIG));
            float x1 = fmaf(a, v.y, fmaf(sm * tm.y, 1e10f, NEG_BIG));
            float x2 = fmaf(a, v.z, fmaf(sm * tm.z, 1e10f, NEG_BIG));
            float x3 = fmaf(a, v.w, fmaf(sm * tm.w, 1e10f, NEG_BIG));
            m = fmaxf(m, fmaxf(fmaxf(x0, x1), fmaxf(x2, x3)));
        }
        pm[tid] = m;
        __syncthreads();
        m = fmaxf(pm[tid], pm[tid ^ 256]);
#pragma unroll 4
        for (int t4 = 0; t4 < 64; t4++) {
            float4 v = vv[t4], tm = tt[t4];
            float x0 = fmaf(a, v.x, fmaf(sm * tm.x, 1e10f, NEG_BIG));
            float x1 = fmaf(a, v.y, fmaf(sm * tm.y, 1e10f, NEG_BIG));
            float x2 = fmaf(a, v.z, fmaf(sm * tm.z, 1e10f, NEG_BIG));
            float x3 = fmaf(a, v.w, fmaf(sm * tm.w, 1e10f, NEG_BIG));
            float e0 = ex2((x0 - m) * LOG2E);
            float e1 = ex2((x1 - m) * LOG2E);
            float e2 = ex2((x2 - m) * LOG2E);
            float e3 = ex2((x3 - m) * LOG2E);
            sum += e0 + e1 + e2 + e3;
            acc = fmaf(e0, v.x, acc);
            acc = fmaf(e1, v.y, acc);
            acc = fmaf(e2, v.z, acc);
            acc = fmaf(e3, v.w, acc);
        }
        ps[tid] = sum; pa[tid] = acc;
        __syncthreads();
    }

    if (tid < 256) {
        float S = ps[tid] + ps[tid + 256];
        float A = pa[tid] + pa[tid + 256];
        c_s[(tid & 31) * Rr + (tid >> 5)] = A / S;
    }
    __syncthreads();

    // Phase B: out tile [32 s][512 d] = c · wn
    {
        int d4 = tid & 127;
        int jg = tid >> 7;
        float4 wv[Rr];
#pragma unroll
        for (int rr = 0; rr < Rr; rr++) wv[rr] = ((const float4*)g_wn)[rr * 128 + d4];

        float4* out4 = (float4*)out;
#pragma unroll
        for (int k = 0; k < 8; k++) {
            int jj = jg + 4 * k;
            float4 o = make_float4(0.f, 0.f, 0.f, 0.f);
#pragma unroll
            for (int rr = 0; rr < Rr; rr++) {
                float c = c_s[jj * Rr + rr];
                o.x = fmaf(c, wv[rr].x, o.x);
                o.y = fmaf(c, wv[rr].y, o.y);
                o.z = fmaf(c, wv[rr].z, o.z);
                o.w = fmaf(c, wv[rr].w, o.w);
            }
            out4[((size_t)b * Ss + s0 + jj) * (Dd / 4) + d4] = o;
        }
    }
}

// ---------------------------------------------------------------------------
extern "C" void kernel_launch(void* const* d_in, const int* in_sizes, int n_in,
                              void* d_out, int out_size) {
    const float* src_emb  = (const float*)d_in[0];
    const float* tar_emb  = (const float*)d_in[1];
    const float* src_mask = (const float*)d_in[2];
    const float* tar_mask = (const float*)d_in[3];
    const float* w        = (const float*)d_in[4];
    float* out            = (float*)d_out;

    k_dots<<<(Bb * Ss + Bb * Tt) / 32, 256>>>(src_emb, tar_emb, w);
    k_attn_out<<<Bb * (Ss / 32), 512>>>(src_mask, tar_mask, out);
}

// round 9
// speedup vs baseline: 1.3053x; 1.1542x over previous
#include <cuda_runtime.h>
#include <cuda_fp16.h>
#include <math.h>

#define Bb 16
#define Ss 512
#define Tt 512
#define Dd 512
#define Rr 8
#define NEG_BIG (-1e10f)
#define LOG2E 1.4426950408889634f

typedef unsigned long long u64;

// scratch (device globals; no allocation allowed)
__device__ float g_sc[Rr];                 // 1/||w_r|| (published by k_dots block 0)
__device__ float g_src_wt[Bb * Rr * Ss];   // [b,r,s]
__device__ float g_tar_wt[Bb * Rr * Tt];   // [b,r,t]

__device__ __forceinline__ float ex2(float x) {
    float y;
    asm("ex2.approx.f32 %0, %1;" : "=f"(y) : "f"(x));
    return y;
}
__device__ __forceinline__ u64 pk(float lo, float hi) {
    u64 d; asm("mov.b64 %0, {%1, %2};" : "=l"(d) : "f"(lo), "f"(hi)); return d;
}
__device__ __forceinline__ void upk(u64 p, float& lo, float& hi) {
    asm("mov.b64 {%0, %1}, %2;" : "=f"(lo), "=f"(hi) : "l"(p));
}
__device__ __forceinline__ u64 ffma2(u64 a, u64 b, u64 c) {
    u64 d; asm("fma.rn.f32x2 %0, %1, %2, %3;" : "=l"(d) : "l"(a), "l"(b), "l"(c)); return d;
}
__device__ __forceinline__ __half2 hex2(__half2 x) {
    unsigned u = *reinterpret_cast<unsigned*>(&x);
    unsigned y;
    asm("ex2.approx.f16x2 %0, %1;" : "=r"(y) : "r"(u));
    return *reinterpret_cast<__half2*>(&y);
}

// ---------------------------------------------------------------------------
// Kernel 1: dot each embedding row with all 8 RAW w rows; scale by 1/||w_r||
// at the store (deferred normalization). 256 threads, 4 rows/warp (w-LDS
// reuse 4), x k=0 prefetched before the w-smem sync, k+1 double-buffered.
// ---------------------------------------------------------------------------
__global__ __launch_bounds__(256, 2) void k_dots(const float* __restrict__ src,
                                                 const float* __restrict__ tar,
                                                 const float* __restrict__ w) {
    __shared__ float4 wn_s[Rr * Dd / 4];  // 16 KB raw w
    __shared__ float  sc_s[Rr];
    int tid  = threadIdx.x;
    int warp = tid >> 5;
    int lane = tid & 31;

    int base = blockIdx.x * 32 + warp * 4;
    bool is_src = base < Bb * Ss;            // blocks never straddle (8192 % 32 == 0)
    const float* eb = is_src ? src : tar;
    int lbase = is_src ? base : base - Bb * Ss;

    // prefetch x (k=0) BEFORE the smem barrier so LDG overlaps preamble
    float4 xa[4], xb[4];
#pragma unroll
    for (int rr = 0; rr < 4; rr++)
        xa[rr] = ((const float4*)(eb + (size_t)(lbase + rr) * Dd))[lane];

#pragma unroll
    for (int i = 0; i < 4; i++)
        wn_s[tid + 256 * i] = ((const float4*)w)[tid + 256 * i];
    __syncthreads();

    // row L2 norms on raw w (warp r reduces row r)
    {
        float ss = 0.f;
#pragma unroll
        for (int k = 0; k < 4; k++) {
            float4 x = wn_s[warp * 128 + lane + 32 * k];
            ss += x.x * x.x + x.y * x.y + x.z * x.z + x.w * x.w;
        }
#pragma unroll
        for (int off = 16; off; off >>= 1)
            ss += __shfl_xor_sync(0xffffffffu, ss, off);
        if (lane == 0) {
            float sc = 1.0f / fmaxf(sqrtf(ss), 1e-12f);
            sc_s[warp] = sc;
            if (blockIdx.x == 0) g_sc[warp] = sc;
        }
    }
    __syncthreads();

    u64 acc2[4][Rr];
#pragma unroll
    for (int rr = 0; rr < 4; rr++)
#pragma unroll
        for (int r = 0; r < Rr; r++) acc2[rr][r] = 0ull;

#pragma unroll
    for (int k = 0; k < 4; k++) {
        if (k < 3) {
#pragma unroll
            for (int rr = 0; rr < 4; rr++)
                xb[rr] = ((const float4*)(eb + (size_t)(lbase + rr) * Dd))[lane + 32 * (k + 1)];
        }
        u64 xp01[4], xp23[4];
#pragma unroll
        for (int rr = 0; rr < 4; rr++) {
            xp01[rr] = pk(xa[rr].x, xa[rr].y);
            xp23[rr] = pk(xa[rr].z, xa[rr].w);
        }
#pragma unroll
        for (int r = 0; r < Rr; r++) {
            float4 wv = wn_s[r * 128 + lane + 32 * k];
            u64 w01 = pk(wv.x, wv.y);
            u64 w23 = pk(wv.z, wv.w);
#pragma unroll
            for (int rr = 0; rr < 4; rr++) {
                acc2[rr][r] = ffma2(xp01[rr], w01, acc2[rr][r]);
                acc2[rr][r] = ffma2(xp23[rr], w23, acc2[rr][r]);
            }
        }
#pragma unroll
        for (int rr = 0; rr < 4; rr++) xa[rr] = xb[rr];
    }

    // fold even/odd, butterfly so acc-index L lands at lane L
    float t[32];
#pragma unroll
    for (int rr = 0; rr < 4; rr++)
#pragma unroll
        for (int r = 0; r < Rr; r++) {
            float lo, hi;
            upk(acc2[rr][r], lo, hi);
            t[rr * 8 + r] = lo + hi;
        }

#pragma unroll
    for (int st = 0; st < 5; st++) {
        int off = 1 << st;
        int sel = lane & off;
#pragma unroll
        for (int j = 0; j < (16 >> st); j++) {
            float give = sel ? t[2 * j]     : t[2 * j + 1];
            float keep = sel ? t[2 * j + 1] : t[2 * j];
            float recv = __shfl_xor_sync(0xffffffffu, give, off);
            t[j] = keep + recv;
        }
    }

    {
        int rr = lane >> 3, r = lane & 7;
        int gid = lbase + rr;
        int bb = gid >> 9, s = gid & 511;
        float* gw = is_src ? g_src_wt : g_tar_wt;
        gw[((size_t)bb * Rr + r) * Ss + s] = t[0] * sc_s[r];
    }
}

// ---------------------------------------------------------------------------
// Kernel 2 (fused attention + output): grid = B*(S/32) = 256 blocks, 512 thr.
// half = tid>>8, r = (tid>>5)&7, j = tid&31.
// Fast path (all masks 1): vd = v - vmax (or vmin) precomputed in smem half2;
// x = a2*vd via HMUL2 (error relative-in-x => benign), exp via ex2.f16x2,
// sum & acc(e*vd) accumulated in 16 fp16 lanes each; recover
// sum(e*v) = sum(e*vd) + vmax*sum(e) exactly in f32.
// Slow path: general two-pass fp32 (block-uniform branch).
// Phase B: out tile [32 s][512 d] = c · (w * g_sc) with w in registers.
// ---------------------------------------------------------------------------
__global__ __launch_bounds__(512, 2) void k_attn_out(const float* __restrict__ src_mask,
                                                     const float* __restrict__ tar_mask,
                                                     const float* __restrict__ w,
                                                     float* __restrict__ out) {
    __shared__ float   v_s[Rr * Tt];        // 16 KB
    __shared__ __half2 vdx_h[Rr * Tt / 2];  // 8 KB: v - vmax[r]
    __shared__ __half2 vdn_h[Rr * Tt / 2];  // 8 KB: v - vmin[r]
    __shared__ float   tm_s[Tt];
    __shared__ float   a_s[Rr * 32];
    __shared__ float   sm_s[32];
    __shared__ float   ps[512], pa[512], pm[512];
    __shared__ float   c_s[32 * Rr];
    __shared__ float   red_max[Rr], red_min[Rr];
    __shared__ int     s_tmok, s_smok;

    int b   = blockIdx.x >> 4;
    int s0  = (blockIdx.x & 15) * 32;
    int tid = threadIdx.x;
    int warp = tid >> 5, lane = tid & 31;
    int half = tid >> 8;
    int r    = (tid >> 5) & 7;
    int j    = tid & 31;

    const float4* vsrc = (const float4*)(g_tar_wt + (size_t)b * Rr * Tt);
    ((float4*)v_s)[tid]       = vsrc[tid];
    ((float4*)v_s)[tid + 512] = vsrc[tid + 512];
    if (tid < 128) ((float4*)tm_s)[tid] = ((const float4*)(tar_mask + (size_t)b * Tt))[tid];
    if (tid < 256) a_s[tid] = g_src_wt[((size_t)b * Rr + (tid >> 5)) * Ss + s0 + (tid & 31)];
    if (tid < 32)  sm_s[tid] = src_mask[(size_t)b * Ss + s0 + tid];
    __syncthreads();

    if (warp < Rr) {
        float cmax = -3.4e38f, cmin = 3.4e38f;
#pragma unroll
        for (int k = 0; k < 16; k++) {
            float v = v_s[warp * 512 + lane + 32 * k];
            cmax = fmaxf(cmax, v);
            cmin = fminf(cmin, v);
        }
#pragma unroll
        for (int off = 16; off; off >>= 1) {
            cmax = fmaxf(cmax, __shfl_xor_sync(0xffffffffu, cmax, off));
            cmin = fminf(cmin, __shfl_xor_sync(0xffffffffu, cmin, off));
        }
        if (lane == 0) { red_max[warp] = cmax; red_min[warp] = cmin; }
    } else if (warp == 8) {
        int one = 1;
#pragma unroll
        for (int k = 0; k < 16; k++)
            one &= (tm_s[lane + 32 * k] == 1.0f);
        one = (__ballot_sync(0xffffffffu, one) == 0xffffffffu);
        if (lane == 0) s_tmok = one;
    } else if (warp == 9) {
        int one = (sm_s[lane] == 1.0f);
        one = (__ballot_sync(0xffffffffu, one) == 0xffffffffu);
        if (lane == 0) s_smok = one;
    }
    __syncthreads();

    // build half2 vd arrays (2 float4 per thread per array)
#pragma unroll
    for (int i = tid; i < Rr * Tt / 4; i += 512) {
        float4 v4 = ((const float4*)v_s)[i];
        int rr = i >> 7;
        float mx = red_max[rr], mn = red_min[rr];
        vdx_h[2 * i]     = __floats2half2_rn(v4.x - mx, v4.y - mx);
        vdx_h[2 * i + 1] = __floats2half2_rn(v4.z - mx, v4.w - mx);
        vdn_h[2 * i]     = __floats2half2_rn(v4.x - mn, v4.y - mn);
        vdn_h[2 * i + 1] = __floats2half2_rn(v4.z - mn, v4.w - mn);
    }
    __syncthreads();

    float a = a_s[tid & 255];
    bool fast = (s_tmok && s_smok);   // block-uniform

    if (fast) {
        const uint4* vp = (const uint4*)((a >= 0.f) ? vdx_h : vdn_h) + r * 64 + half * 32;
        __half2 a2h = __half2half2(__float2half_rn(a * LOG2E));
        __half2 sh[8], qh[8];
#pragma unroll
        for (int i = 0; i < 8; i++) { sh[i] = __half2half2(__ushort_as_half(0)); qh[i] = sh[i]; }

#pragma unroll
        for (int it = 0; it < 32; it += 2) {
            uint4 u0 = vp[it];
            uint4 u1 = vp[it + 1];
            __half2 v0 = *reinterpret_cast<__half2*>(&u0.x);
            __half2 v1 = *reinterpret_cast<__half2*>(&u0.y);
            __half2 v2 = *reinterpret_cast<__half2*>(&u0.z);
            __half2 v3 = *reinterpret_cast<__half2*>(&u0.w);
            __half2 e0 = hex2(__hmul2(a2h, v0));
            __half2 e1 = hex2(__hmul2(a2h, v1));
            __half2 e2 = hex2(__hmul2(a2h, v2));
            __half2 e3 = hex2(__hmul2(a2h, v3));
            sh[0] = __hadd2(sh[0], e0);
            sh[1] = __hadd2(sh[1], e1);
            sh[2] = __hadd2(sh[2], e2);
            sh[3] = __hadd2(sh[3], e3);
            qh[0] = __hfma2(e0, v0, qh[0]);
            qh[1] = __hfma2(e1, v1, qh[1]);
            qh[2] = __hfma2(e2, v2, qh[2]);
            qh[3] = __hfma2(e3, v3, qh[3]);
            __half2 w0 = *reinterpret_cast<__half2*>(&u1.x);
            __half2 w1 = *reinterpret_cast<__half2*>(&u1.y);
            __half2 w2 = *reinterpret_cast<__half2*>(&u1.z);
            __half2 w3 = *reinterpret_cast<__half2*>(&u1.w);
            __half2 f0 = hex2(__hmul2(a2h, w0));
            __half2 f1 = hex2(__hmul2(a2h, w1));
            __half2 f2 = hex2(__hmul2(a2h, w2));
            __half2 f3 = hex2(__hmul2(a2h, w3));
            sh[4] = __hadd2(sh[4], f0);
            sh[5] = __hadd2(sh[5], f1);
            sh[6] = __hadd2(sh[6], f2);
            sh[7] = __hadd2(sh[7], f3);
            qh[4] = __hfma2(f0, w0, qh[4]);
            qh[5] = __hfma2(f1, w1, qh[5]);
            qh[6] = __hfma2(f2, w2, qh[6]);
            qh[7] = __hfma2(f3, w3, qh[7]);
        }
        float S = 0.f, A = 0.f;
#pragma unroll
        for (int i = 0; i < 8; i++) {
            float2 fs = __half22float2(sh[i]);
            float2 fq = __half22float2(qh[i]);
            S += fs.x + fs.y;
            A += fq.x + fq.y;
        }
        ps[tid] = S; pa[tid] = A;
        __syncthreads();
    } else {
        const float4* vv = (const float4*)(v_s + r * Tt) + half * 64;
        const float4* tt = (const float4*)tm_s + half * 64;
        float sm = sm_s[j];
        float sum = 0.f, acc = 0.f;
        float m = -3.4e38f;
#pragma unroll 4
        for (int t4 = 0; t4 < 64; t4++) {
            float4 v = vv[t4], tm = tt[t4];
            float x0 = fmaf(a, v.x, fmaf(sm * tm.x, 1e10f, NEG_BIG));
            float x1 = fmaf(a, v.y, fmaf(sm * tm.y, 1e10f, NEG_BIG));
            float x2 = fmaf(a, v.z, fmaf(sm * tm.z, 1e10f, NEG_BIG));
            float x3 = fmaf(a, v.w, fmaf(sm * tm.w, 1e10f, NEG_BIG));
            m = fmaxf(m, fmaxf(fmaxf(x0, x1), fmaxf(x2, x3)));
        }
        pm[tid] = m;
        __syncthreads();
        m = fmaxf(pm[tid], pm[tid ^ 256]);
#pragma unroll 4
        for (int t4 = 0; t4 < 64; t4++) {
            float4 v = vv[t4], tm = tt[t4];
            float x0 = fmaf(a, v.x, fmaf(sm * tm.x, 1e10f, NEG_BIG));
            float x1 = fmaf(a, v.y, fmaf(sm * tm.y, 1e10f, NEG_BIG));
            float x2 = fmaf(a, v.z, fmaf(sm * tm.z, 1e10f, NEG_BIG));
            float x3 = fmaf(a, v.w, fmaf(sm * tm.w, 1e10f, NEG_BIG));
            float e0 = ex2((x0 - m) * LOG2E);
            float e1 = ex2((x1 - m) * LOG2E);
            float e2 = ex2((x2 - m) * LOG2E);
            float e3 = ex2((x3 - m) * LOG2E);
            sum += e0 + e1 + e2 + e3;
            acc = fmaf(e0, v.x, acc);
            acc = fmaf(e1, v.y, acc);
            acc = fmaf(e2, v.z, acc);
            acc = fmaf(e3, v.w, acc);
        }
        ps[tid] = sum; pa[tid] = acc;
        __syncthreads();
    }

    if (tid < 256) {
        float S = ps[tid] + ps[tid + 256];
        float A = pa[tid] + pa[tid + 256];
        float c = A / S;
        if (fast) {
            float aa = a_s[tid];
            c += (aa >= 0.f) ? red_max[tid >> 5] : red_min[tid >> 5];
        }
        c_s[(tid & 31) * Rr + (tid >> 5)] = c;
    }
    __syncthreads();

    // Phase B: out tile [32 s][512 d] = c · (w * g_sc)
    {
        int d4 = tid & 127;
        int jg = tid >> 7;
        float4 wv[Rr];
#pragma unroll
        for (int rr = 0; rr < Rr; rr++) {
            float4 ww = ((const float4*)w)[rr * 128 + d4];
            float sc = g_sc[rr];
            ww.x *= sc; ww.y *= sc; ww.z *= sc; ww.w *= sc;
            wv[rr] = ww;
        }

        float4* out4 = (float4*)out;
#pragma unroll
        for (int k = 0; k < 8; k++) {
            int jj = jg + 4 * k;
            float4 o = make_float4(0.f, 0.f, 0.f, 0.f);
#pragma unroll
            for (int rr = 0; rr < Rr; rr++) {
                float c = c_s[jj * Rr + rr];
                o.x = fmaf(c, wv[rr].x, o.x);
                o.y = fmaf(c, wv[rr].y, o.y);
                o.z = fmaf(c, wv[rr].z, o.z);
                o.w = fmaf(c, wv[rr].w, o.w);
            }
            out4[((size_t)b * Ss + s0 + jj) * (Dd / 4) + d4] = o;
        }
    }
}

// ---------------------------------------------------------------------------
extern "C" void kernel_launch(void* const* d_in, const int* in_sizes, int n_in,
                              void* d_out, int out_size) {
    const float* src_emb  = (const float*)d_in[0];
    const float* tar_emb  = (const float*)d_in[1];
    const float* src_mask = (const float*)d_in[2];
    const float* tar_mask = (const float*)d_in[3];
    const float* w        = (const float*)d_in[4];
    float* out            = (float*)d_out;

    k_dots<<<(Bb * Ss + Bb * Tt) / 32, 256>>>(src_emb, tar_emb, w);
    k_attn_out<<<Bb * (Ss / 32), 512>>>(src_mask, tar_mask, w, out);
}